// round 4
// baseline (speedup 1.0000x reference)
#include <cuda_runtime.h>
#include <cuda_bf16.h>
#include <cstdint>

#define NR 4096
#define DD 512
#define TAU_INV 10.0f

// ---------------- scratch (static device globals; no allocs) ----------------
__device__ __nv_bfloat16 g_A[NR * DD];   // normalized features, bf16
__device__ float g_denom[NR];
__device__ float g_pos[NR];
__device__ int   g_lab[NR];

// ---------------- kernel 0: label decode (int32 vs int64 autodetect) --------
__global__ void label_kernel(const int* __restrict__ p32) {
    __shared__ int nonzero_odd;
    if (threadIdx.x == 0) nonzero_odd = 0;
    __syncthreads();
    // int64 little-endian labels in [0,100) -> all odd 32-bit words are 0.
    for (int i = 1 + 2 * threadIdx.x; i < 2048; i += 2 * blockDim.x)
        if (p32[i] != 0) nonzero_odd = 1;
    __syncthreads();
    bool is64 = (nonzero_odd == 0);
    for (int i = threadIdx.x; i < NR; i += blockDim.x)
        g_lab[i] = is64 ? p32[2 * i] : p32[i];
}

// ---------------- kernel 1: row norms + bf16 normalize + zero accumulators --
__global__ __launch_bounds__(256) void prep_kernel(const float* __restrict__ f) {
    int row = blockIdx.x;
    const float* fr = f + row * DD;
    float v0 = fr[threadIdx.x];
    float v1 = fr[threadIdx.x + 256];
    float s = v0 * v0 + v1 * v1;
    __shared__ float red[8];
    #pragma unroll
    for (int o = 16; o; o >>= 1) s += __shfl_xor_sync(~0u, s, o);
    if ((threadIdx.x & 31) == 0) red[threadIdx.x >> 5] = s;
    __syncthreads();
    if (threadIdx.x < 8) {
        float v = red[threadIdx.x];
        #pragma unroll
        for (int o = 4; o; o >>= 1) v += __shfl_xor_sync(0xffu, v, o);
        if (threadIdx.x == 0) red[0] = v;
    }
    __syncthreads();
    float inv = 1.0f / sqrtf(red[0]);
    g_A[row * DD + threadIdx.x]       = __float2bfloat16(v0 * inv);
    g_A[row * DD + threadIdx.x + 256] = __float2bfloat16(v1 * inv);
    if (threadIdx.x == 0) { g_denom[row] = 0.f; g_pos[row] = 0.f; }
}

// ---------------- kernel 2: fused GEMM (A A^T) + contrastive epilogue -------
// Symmetric: only tiles bx >= by are computed; off-diagonal tiles contribute
// both row sums (this tile's rows) and column sums (mirror tile's rows).
// Tile 128x128, BK=32, 8 warps (2x4), warp tile 64x32, mma.m16n8k16 bf16.
#define PK 40  // padded K stride in bf16 elems (80B rows: 16B-aligned, conflict-free)

__device__ __forceinline__ void mma16816(float* c, const uint32_t* a, const uint32_t* b) {
    asm volatile(
        "mma.sync.aligned.m16n8k16.row.col.f32.bf16.bf16.f32 "
        "{%0,%1,%2,%3}, {%4,%5,%6,%7}, {%8,%9}, {%0,%1,%2,%3};\n"
        : "+f"(c[0]), "+f"(c[1]), "+f"(c[2]), "+f"(c[3])
        : "r"(a[0]), "r"(a[1]), "r"(a[2]), "r"(a[3]), "r"(b[0]), "r"(b[1]));
}

__global__ __launch_bounds__(256) void gemm_kernel() {
    if (blockIdx.x < blockIdx.y) return;   // symmetric: lower-left tiles skipped
    const bool offDiag = (blockIdx.x != blockIdx.y);

    __shared__ __nv_bfloat16 shA[128 * PK];
    __shared__ __nv_bfloat16 shB[128 * PK];
    __shared__ float sh_pd[4][128];
    __shared__ float sh_pp[4][128];
    __shared__ float sh_cd[2][128];
    __shared__ float sh_cp[2][128];
    __shared__ int labR[128], labC[128];

    const int tid  = threadIdx.x;
    const int lane = tid & 31, warp = tid >> 5;
    const int wm = warp >> 2, wn = warp & 3;       // 2x4 warp grid
    const int g = lane >> 2, t = lane & 3;
    const int rowBase = blockIdx.y * 128;
    const int colBase = blockIdx.x * 128;

    if (tid < 128) labR[tid] = g_lab[rowBase + tid];
    else           labC[tid - 128] = g_lab[colBase + tid - 128];

    float acc[4][4][4];
    #pragma unroll
    for (int mi = 0; mi < 4; mi++)
        #pragma unroll
        for (int ni = 0; ni < 4; ni++)
            #pragma unroll
            for (int r = 0; r < 4; r++) acc[mi][ni][r] = 0.f;

    // global->reg staging: each thread owns chunks (tid*2, tid*2+1); chunk c:
    // row = c>>2, 16B piece w = c&3
    const int cA = tid * 2;
    const int rA0 = cA >> 2,       wA0 = cA & 3;
    const int rA1 = (cA + 1) >> 2, wA1 = (cA + 1) & 3;

    float4 ra0, ra1, rb0, rb1;
    #define GLD(dst, rbase, r, w, kt) \
        dst = *(const float4*)(&g_A[((rbase) + (r)) * DD + (kt) * 32 + (w) * 8]);

    GLD(ra0, rowBase, rA0, wA0, 0); GLD(ra1, rowBase, rA1, wA1, 0);
    GLD(rb0, colBase, rA0, wA0, 0); GLD(rb1, colBase, rA1, wA1, 0);

    for (int kt = 0; kt < 16; kt++) {
        *(float4*)&shA[rA0 * PK + wA0 * 8] = ra0;
        *(float4*)&shA[rA1 * PK + wA1 * 8] = ra1;
        *(float4*)&shB[rA0 * PK + wA0 * 8] = rb0;
        *(float4*)&shB[rA1 * PK + wA1 * 8] = rb1;
        __syncthreads();
        if (kt < 15) {
            GLD(ra0, rowBase, rA0, wA0, kt + 1); GLD(ra1, rowBase, rA1, wA1, kt + 1);
            GLD(rb0, colBase, rA0, wA0, kt + 1); GLD(rb1, colBase, rA1, wA1, kt + 1);
        }
        #pragma unroll
        for (int kk = 0; kk < 32; kk += 16) {
            uint32_t af[4][4], bfr[4][2];
            #pragma unroll
            for (int mi = 0; mi < 4; mi++) {
                int rm = wm * 64 + mi * 16;
                af[mi][0] = *(const uint32_t*)&shA[(rm + g)     * PK + kk +     2 * t];
                af[mi][1] = *(const uint32_t*)&shA[(rm + g + 8) * PK + kk +     2 * t];
                af[mi][2] = *(const uint32_t*)&shA[(rm + g)     * PK + kk + 8 + 2 * t];
                af[mi][3] = *(const uint32_t*)&shA[(rm + g + 8) * PK + kk + 8 + 2 * t];
            }
            #pragma unroll
            for (int ni = 0; ni < 4; ni++) {
                int rn = wn * 32 + ni * 8;
                bfr[ni][0] = *(const uint32_t*)&shB[(rn + g) * PK + kk +     2 * t];
                bfr[ni][1] = *(const uint32_t*)&shB[(rn + g) * PK + kk + 8 + 2 * t];
            }
            #pragma unroll
            for (int mi = 0; mi < 4; mi++)
                #pragma unroll
                for (int ni = 0; ni < 4; ni++)
                    mma16816(acc[mi][ni], af[mi], bfr[ni]);
        }
        __syncthreads();
    }

    // ---- epilogue: sim = acc/tau; row sums always, column sums if offDiag ----
    float colPD[4][2], colPP[4][2];
    #pragma unroll
    for (int ni = 0; ni < 4; ni++) {
        colPD[ni][0] = colPD[ni][1] = 0.f;
        colPP[ni][0] = colPP[ni][1] = 0.f;
    }

    #pragma unroll
    for (int mi = 0; mi < 4; mi++) {
        #pragma unroll
        for (int h = 0; h < 2; h++) {
            int lr = wm * 64 + mi * 16 + g + 8 * h;   // local row in block
            int gi = rowBase + lr;
            int myLab = labR[lr];
            float pd = 0.f, pp = 0.f;
            #pragma unroll
            for (int ni = 0; ni < 4; ni++) {
                int lc = wn * 32 + ni * 8 + 2 * t;
                float s0 = acc[mi][ni][2 * h]     * TAU_INV;
                float s1 = acc[mi][ni][2 * h + 1] * TAU_INV;
                int gj0 = colBase + lc;
                int cl0 = labC[lc], cl1 = labC[lc + 1];
                float e0 = __expf(s0), e1 = __expf(s1);
                bool m0 = (cl0 == myLab), m1 = (cl1 == myLab);
                if (gj0 != gi)     { pd += e0; if (m0) pp += s0; }
                if (gj0 + 1 != gi) { pd += e1; if (m1) pp += s1; }
                if (offDiag) {
                    colPD[ni][0] += e0; colPD[ni][1] += e1;
                    if (m0) colPP[ni][0] += s0;
                    if (m1) colPP[ni][1] += s1;
                }
            }
            pd += __shfl_xor_sync(~0u, pd, 1); pd += __shfl_xor_sync(~0u, pd, 2);
            pp += __shfl_xor_sync(~0u, pp, 1); pp += __shfl_xor_sync(~0u, pp, 2);
            if (t == 0) { sh_pd[wn][lr] = pd; sh_pp[wn][lr] = pp; }
        }
    }

    // column reduction: over g (lane bits 2,3,4), then over wm via smem
    if (offDiag) {
        #pragma unroll
        for (int ni = 0; ni < 4; ni++) {
            #pragma unroll
            for (int c = 0; c < 2; c++) {
                float vd = colPD[ni][c], vp = colPP[ni][c];
                #pragma unroll
                for (int o = 4; o <= 16; o <<= 1) {
                    vd += __shfl_xor_sync(~0u, vd, o);
                    vp += __shfl_xor_sync(~0u, vp, o);
                }
                if (g == 0) {
                    int lc = wn * 32 + ni * 8 + 2 * t + c;
                    sh_cd[wm][lc] = vd;
                    sh_cp[wm][lc] = vp;
                }
            }
        }
    }
    __syncthreads();
    if (tid < 128) {
        float d = sh_pd[0][tid] + sh_pd[1][tid] + sh_pd[2][tid] + sh_pd[3][tid];
        float p = sh_pp[0][tid] + sh_pp[1][tid] + sh_pp[2][tid] + sh_pp[3][tid];
        atomicAdd(&g_denom[rowBase + tid], d);
        atomicAdd(&g_pos[rowBase + tid], p);
    } else if (offDiag) {
        int j = tid - 128;
        atomicAdd(&g_denom[colBase + j], sh_cd[0][j] + sh_cd[1][j]);
        atomicAdd(&g_pos[colBase + j],   sh_cp[0][j] + sh_cp[1][j]);
    }
}

// ---------------- kernel 3: finalize ----------------------------------------
__global__ __launch_bounds__(512) void finalize_kernel(float* __restrict__ out) {
    __shared__ int hist[128];
    __shared__ float red[16];
    int tid = threadIdx.x;
    if (tid < 128) hist[tid] = 0;
    __syncthreads();
    for (int i = tid; i < NR; i += blockDim.x) atomicAdd(&hist[g_lab[i] & 127], 1);
    __syncthreads();
    float s = 0.f;
    for (int i = tid; i < NR; i += blockDim.x) {
        float cnt = (float)(hist[g_lab[i] & 127] - 1);
        s += (g_pos[i] - cnt * logf(g_denom[i])) / (cnt + 1e-8f);
    }
    #pragma unroll
    for (int o = 16; o; o >>= 1) s += __shfl_xor_sync(~0u, s, o);
    if ((tid & 31) == 0) red[tid >> 5] = s;
    __syncthreads();
    if (tid < 32) {
        float v = (tid < 16) ? red[tid] : 0.f;
        #pragma unroll
        for (int o = 16; o; o >>= 1) v += __shfl_xor_sync(~0u, v, o);
        if (tid == 0) out[0] = -v / (float)NR;
    }
}

// ---------------- launch -----------------------------------------------------
extern "C" void kernel_launch(void* const* d_in, const int* in_sizes, int n_in,
                              void* d_out, int out_size) {
    const float* f   = (const float*)d_in[0];
    const int*   lab = (const int*)d_in[1];   // int32 or int64, autodetected
    float* out = (float*)d_out;

    label_kernel<<<1, 256>>>(lab);
    prep_kernel<<<NR, 256>>>(f);
    dim3 grid(NR / 128, NR / 128);
    gemm_kernel<<<grid, 256>>>();
    finalize_kernel<<<1, 512>>>(out);
}

// round 6
// speedup vs baseline: 1.2550x; 1.2550x over previous
#include <cuda_runtime.h>
#include <cuda_bf16.h>
#include <cstdint>

#define NR 4096
#define DD 512
#define TAU_INV 10.0f
#define PK 40                      // padded K stride (80B rows, conflict-free)
#define TILEB (128 * PK * 2)       // bytes per tile stage

// ---------------- scratch (static device globals; no allocs) ----------------
__device__ __nv_bfloat16 g_A[NR * DD];   // normalized features, bf16
__device__ float g_denom[NR];
__device__ float g_pos[NR];
__device__ int   g_lab[NR];
__device__ int   g_hist[128];
__device__ float g_loss;
__device__ int   g_done;

// ---------------- PTX helpers ------------------------------------------------
__device__ __forceinline__ void cp16(uint32_t dst, const void* src) {
    asm volatile("cp.async.cg.shared.global [%0], [%1], 16;\n"
                 :: "r"(dst), "l"(src) : "memory");
}
__device__ __forceinline__ void cp_commit() {
    asm volatile("cp.async.commit_group;\n" ::: "memory");
}
__device__ __forceinline__ void cp_wait0() {
    asm volatile("cp.async.wait_group 0;\n" ::: "memory");
}
__device__ __forceinline__ void ldsm4(uint32_t* r, uint32_t addr) {
    asm volatile("ldmatrix.sync.aligned.m8n8.x4.shared.b16 {%0,%1,%2,%3}, [%4];\n"
        : "=r"(r[0]), "=r"(r[1]), "=r"(r[2]), "=r"(r[3]) : "r"(addr) : "memory");
}
__device__ __forceinline__ void mma16816(float* c, const uint32_t* a, const uint32_t* b) {
    asm volatile(
        "mma.sync.aligned.m16n8k16.row.col.f32.bf16.bf16.f32 "
        "{%0,%1,%2,%3}, {%4,%5,%6,%7}, {%8,%9}, {%0,%1,%2,%3};\n"
        : "+f"(c[0]), "+f"(c[1]), "+f"(c[2]), "+f"(c[3])
        : "r"(a[0]), "r"(a[1]), "r"(a[2]), "r"(a[3]), "r"(b[0]), "r"(b[1]));
}

// ---------------- kernel 0: label decode + histogram + zero globals ----------
__global__ __launch_bounds__(256) void label_kernel(const int* __restrict__ p32) {
    __shared__ int hist[128];
    __shared__ int nonzero_odd;
    int tid = threadIdx.x;
    if (tid == 0) { nonzero_odd = 0; g_loss = 0.f; g_done = 0; }
    if (tid < 128) hist[tid] = 0;
    __syncthreads();
    // int64 little-endian labels in [0,100) -> all odd 32-bit words are 0.
    for (int i = 1 + 2 * tid; i < 2048; i += 512)
        if (p32[i] != 0) nonzero_odd = 1;
    __syncthreads();
    bool is64 = (nonzero_odd == 0);
    for (int i = tid; i < NR; i += 256) {
        int L = is64 ? p32[2 * i] : p32[i];
        g_lab[i] = L;
        atomicAdd(&hist[L & 127], 1);
    }
    __syncthreads();
    if (tid < 128) g_hist[tid] = hist[tid];
}

// ---------------- kernel 1: row norms + bf16 normalize + zero accumulators --
__global__ __launch_bounds__(256) void prep_kernel(const float* __restrict__ f) {
    int row = blockIdx.x;
    const float* fr = f + row * DD;
    float v0 = fr[threadIdx.x];
    float v1 = fr[threadIdx.x + 256];
    float s = v0 * v0 + v1 * v1;
    __shared__ float red[8];
    #pragma unroll
    for (int o = 16; o; o >>= 1) s += __shfl_xor_sync(~0u, s, o);
    if ((threadIdx.x & 31) == 0) red[threadIdx.x >> 5] = s;
    __syncthreads();
    if (threadIdx.x < 8) {
        float v = red[threadIdx.x];
        #pragma unroll
        for (int o = 4; o; o >>= 1) v += __shfl_xor_sync(0xffu, v, o);
        if (threadIdx.x == 0) red[0] = v;
    }
    __syncthreads();
    float inv = 1.0f / sqrtf(red[0]);
    g_A[row * DD + threadIdx.x]       = __float2bfloat16(v0 * inv);
    g_A[row * DD + threadIdx.x + 256] = __float2bfloat16(v1 * inv);
    if (threadIdx.x == 0) { g_denom[row] = 0.f; g_pos[row] = 0.f; }
}

// ---------------- kernel 2: fused symmetric GEMM + contrastive epilogue -----
// 528 CTAs = upper triangle of 32x32 tiles. Tile 128x128, BK=32, double-
// buffered cp.async, ldmatrix fragment loads, 8 warps (2x4), mma.m16n8k16.
__global__ __launch_bounds__(256, 2) void gemm_kernel() {
    // linear block index -> triangular (by, bx), bx >= by (exact integer decode;
    // row r of the upper triangle holds 32-r tiles)
    int rem = blockIdx.x;
    int by = 0;
    #pragma unroll 1
    while (rem >= 32 - by) { rem -= 32 - by; by++; }
    int bx = by + rem;
    const bool offDiag = (bx != by);

    __shared__ __nv_bfloat16 shA[2][128 * PK];
    __shared__ __nv_bfloat16 shB[2][128 * PK];
    __shared__ float sh_pd[4][128];
    __shared__ float sh_pp[4][128];
    __shared__ float sh_cd[2][128];
    __shared__ float sh_cp[2][128];
    __shared__ int labR[128], labC[128];

    const int tid  = threadIdx.x;
    const int lane = tid & 31, warp = tid >> 5;
    const int wm = warp >> 2, wn = warp & 3;       // 2x4 warp grid
    const int g = lane >> 2, t = lane & 3;
    const int rowBase = by * 128;
    const int colBase = bx * 128;

    if (tid < 128) labR[tid] = g_lab[rowBase + tid];
    else           labC[tid - 128] = g_lab[colBase + tid - 128];

    float acc[4][4][4];
    #pragma unroll
    for (int mi = 0; mi < 4; mi++)
        #pragma unroll
        for (int ni = 0; ni < 4; ni++)
            #pragma unroll
            for (int r = 0; r < 4; r++) acc[mi][ni][r] = 0.f;

    // staging: each thread owns chunks (tid*2, tid*2+1); chunk c:
    // row = c>>2, 16B piece w = c&3
    const int cA  = tid * 2;
    const int rA0 = cA >> 2,       wA0 = cA & 3;
    const int rA1 = (cA + 1) >> 2, wA1 = (cA + 1) & 3;

    const uint32_t sA = (uint32_t)__cvta_generic_to_shared(&shA[0][0]);
    const uint32_t sB = (uint32_t)__cvta_generic_to_shared(&shB[0][0]);
    const uint32_t dA0 = sA + (rA0 * PK + wA0 * 8) * 2;
    const uint32_t dA1 = sA + (rA1 * PK + wA1 * 8) * 2;
    const uint32_t dB0 = sB + (rA0 * PK + wA0 * 8) * 2;
    const uint32_t dB1 = sB + (rA1 * PK + wA1 * 8) * 2;
    const __nv_bfloat16* pA0 = &g_A[(rowBase + rA0) * DD + wA0 * 8];
    const __nv_bfloat16* pA1 = &g_A[(rowBase + rA1) * DD + wA1 * 8];
    const __nv_bfloat16* pB0 = &g_A[(colBase + rA0) * DD + wA0 * 8];
    const __nv_bfloat16* pB1 = &g_A[(colBase + rA1) * DD + wA1 * 8];

    // ldmatrix per-thread byte offsets
    const uint32_t offA = (((lane & 15) * PK) + ((lane >> 4) << 3)) * 2;
    const uint32_t offB = ((((lane & 7) + ((lane >> 4) << 3)) * PK) + (((lane >> 3) & 1) << 3)) * 2;
    const uint32_t aBase = sA + offA + (wm * 64) * PK * 2;
    const uint32_t bBase = sB + offB + (wn * 32) * PK * 2;

    // prologue: stage 0
    cp16(dA0, pA0); cp16(dA1, pA1); cp16(dB0, pB0); cp16(dB1, pB1);
    cp_commit();

    for (int kt = 0; kt < 16; kt++) {
        cp_wait0();
        __syncthreads();
        if (kt < 15) {
            uint32_t st = ((kt + 1) & 1) * TILEB;
            int ko = (kt + 1) * 32;
            cp16(dA0 + st, pA0 + ko); cp16(dA1 + st, pA1 + ko);
            cp16(dB0 + st, pB0 + ko); cp16(dB1 + st, pB1 + ko);
            cp_commit();
        }
        uint32_t stg = (kt & 1) * TILEB;
        #pragma unroll
        for (int kk = 0; kk < 32; kk += 16) {
            uint32_t af[4][4], bq[2][4];
            #pragma unroll
            for (int mi = 0; mi < 4; mi++)
                ldsm4(af[mi], aBase + stg + (mi * 16 * PK + kk) * 2);
            #pragma unroll
            for (int p = 0; p < 2; p++)
                ldsm4(bq[p], bBase + stg + (p * 16 * PK + kk) * 2);
            #pragma unroll
            for (int mi = 0; mi < 4; mi++) {
                #pragma unroll
                for (int p = 0; p < 2; p++) {
                    mma16816(acc[mi][2 * p],     af[mi], &bq[p][0]);
                    mma16816(acc[mi][2 * p + 1], af[mi], &bq[p][2]);
                }
            }
        }
    }
    __syncthreads();

    // ---- epilogue: sim = acc/tau; row sums always, column sums if offDiag ----
    float colPD[4][2], colPP[4][2];
    #pragma unroll
    for (int ni = 0; ni < 4; ni++) {
        colPD[ni][0] = colPD[ni][1] = 0.f;
        colPP[ni][0] = colPP[ni][1] = 0.f;
    }

    #pragma unroll
    for (int mi = 0; mi < 4; mi++) {
        #pragma unroll
        for (int h = 0; h < 2; h++) {
            int lr = wm * 64 + mi * 16 + g + 8 * h;   // local row in block
            int gi = rowBase + lr;
            int myLab = labR[lr];
            float pd = 0.f, pp = 0.f;
            #pragma unroll
            for (int ni = 0; ni < 4; ni++) {
                int lc = wn * 32 + ni * 8 + 2 * t;
                float s0 = acc[mi][ni][2 * h]     * TAU_INV;
                float s1 = acc[mi][ni][2 * h + 1] * TAU_INV;
                int gj0 = colBase + lc;
                int cl0 = labC[lc], cl1 = labC[lc + 1];
                float e0 = __expf(s0), e1 = __expf(s1);
                bool m0 = (cl0 == myLab), m1 = (cl1 == myLab);
                if (gj0 != gi)     { pd += e0; if (m0) pp += s0; }
                if (gj0 + 1 != gi) { pd += e1; if (m1) pp += s1; }
                if (offDiag) {
                    colPD[ni][0] += e0; colPD[ni][1] += e1;
                    if (m0) colPP[ni][0] += s0;
                    if (m1) colPP[ni][1] += s1;
                }
            }
            pd += __shfl_xor_sync(~0u, pd, 1); pd += __shfl_xor_sync(~0u, pd, 2);
            pp += __shfl_xor_sync(~0u, pp, 1); pp += __shfl_xor_sync(~0u, pp, 2);
            if (t == 0) { sh_pd[wn][lr] = pd; sh_pp[wn][lr] = pp; }
        }
    }

    // column reduction: over g (lane bits 2,3,4), then over wm via smem
    if (offDiag) {
        #pragma unroll
        for (int ni = 0; ni < 4; ni++) {
            #pragma unroll
            for (int c = 0; c < 2; c++) {
                float vd = colPD[ni][c], vp = colPP[ni][c];
                #pragma unroll
                for (int o = 4; o <= 16; o <<= 1) {
                    vd += __shfl_xor_sync(~0u, vd, o);
                    vp += __shfl_xor_sync(~0u, vp, o);
                }
                if (g == 0) {
                    int lc = wn * 32 + ni * 8 + 2 * t + c;
                    sh_cd[wm][lc] = vd;
                    sh_cp[wm][lc] = vp;
                }
            }
        }
    }
    __syncthreads();
    if (tid < 128) {
        float d = sh_pd[0][tid] + sh_pd[1][tid] + sh_pd[2][tid] + sh_pd[3][tid];
        float p = sh_pp[0][tid] + sh_pp[1][tid] + sh_pp[2][tid] + sh_pp[3][tid];
        atomicAdd(&g_denom[rowBase + tid], d);
        atomicAdd(&g_pos[rowBase + tid], p);
    } else if (offDiag) {
        int j = tid - 128;
        atomicAdd(&g_denom[colBase + j], sh_cd[0][j] + sh_cd[1][j]);
        atomicAdd(&g_pos[colBase + j],   sh_cp[0][j] + sh_cp[1][j]);
    }
}

// ---------------- kernel 3: finalize (32 blocks, last-block writes out) -----
__global__ __launch_bounds__(128) void finalize_kernel(float* __restrict__ out) {
    __shared__ float red[4];
    __shared__ bool isLast;
    int tid = threadIdx.x;
    int i = blockIdx.x * 128 + tid;
    float cnt = (float)(g_hist[g_lab[i] & 127] - 1);
    float s = (g_pos[i] - cnt * __logf(g_denom[i])) / (cnt + 1e-8f);
    #pragma unroll
    for (int o = 16; o; o >>= 1) s += __shfl_xor_sync(~0u, s, o);
    if ((tid & 31) == 0) red[tid >> 5] = s;
    __syncthreads();
    if (tid == 0) {
        float v = red[0] + red[1] + red[2] + red[3];
        atomicAdd(&g_loss, v);
        __threadfence();
        int tck = atomicAdd(&g_done, 1);
        isLast = (tck == 31);
    }
    __syncthreads();
    if (isLast && tid == 0)
        out[0] = -atomicAdd(&g_loss, 0.0f) / (float)NR;
}

// ---------------- launch -----------------------------------------------------
extern "C" void kernel_launch(void* const* d_in, const int* in_sizes, int n_in,
                              void* d_out, int out_size) {
    const float* f   = (const float*)d_in[0];
    const int*   lab = (const int*)d_in[1];   // int32 or int64, autodetected
    float* out = (float*)d_out;

    label_kernel<<<1, 256>>>(lab);
    prep_kernel<<<NR, 256>>>(f);
    gemm_kernel<<<528, 256>>>();
    finalize_kernel<<<32, 128>>>(out);
}